// round 4
// baseline (speedup 1.0000x reference)
#include <cuda_runtime.h>
#include <cuda_bf16.h>
#include <cstdint>

// ============================================================================
// out[M,N] = X[M,K] @ sign(W)[N,K]^T + bias[N],  M=N=K=4096, fp32.
// sm_103 plain PTX target (no tcgen05) => legacy mma.sync path.
//
// Numerics: fixed-scale two-level int8 quantization of X:
//   q1 = round(16*x)  (s8, |x|<7.9 covered; data max ~5.4)
//   q2 = round(256*(16*x - q1))  (s8)
//   x  ≈ (q1 + q2/256)/16,  abs err <= 2^-13  → norm rel err ~7e-5
// sign(W) ∈ {-1,0,+1} exact in s8. Both GEMM passes are EXACT s32 IMMA:
//   out = S1/16 + S2/4096 + bias
// One kernel, unified 64-chunk pipeline (chunks 0..31 = q1, 32..63 = q2),
// S1 folded into out mid-kernel (same-thread RMW, no sync needed).
// ============================================================================

static constexpr int MM = 4096;
static constexpr int NN = 4096;
static constexpr int KK = 4096;

static constexpr int BM = 128;
static constexpr int BN = 256;
static constexpr int BK = 128;            // 128 s8 = 128B row
static constexpr int STAGES = 4;
static constexpr int CHUNKS_PER_PASS = KK / BK;     // 32
static constexpr int TOTAL_CHUNKS = 2 * CHUNKS_PER_PASS; // 64
static constexpr int THREADS = 256;       // 8 warps: 2 (M) x 4 (N), warp 64x64

// SMEM stage layout (bytes)
static constexpr int A_BYTES = BM * 128;            // 16384
static constexpr int B_BYTES = BN * 128;            // 32768
static constexpr int A_OFF = 0;
static constexpr int B_OFF = A_BYTES;
static constexpr int STAGE_BYTES = A_BYTES + B_BYTES;   // 49152
static constexpr int SMEM_TOTAL = STAGES * STAGE_BYTES; // 196608

// ---------------------------------------------------------------------------
// Scratch (allocation-free)
// ---------------------------------------------------------------------------
__device__ __align__(1024) int8_t g_q1[(size_t)MM * KK];
__device__ __align__(1024) int8_t g_q2[(size_t)MM * KK];
__device__ __align__(1024) int8_t g_ws[(size_t)NN * KK];

// ---------------------------------------------------------------------------
// helpers
// ---------------------------------------------------------------------------
__device__ __forceinline__ uint32_t smem_u32(const void* p) {
    uint32_t a;
    asm("{ .reg .u64 t; cvta.to.shared.u64 t, %1; cvt.u32.u64 %0, t; }"
        : "=r"(a) : "l"(p));
    return a;
}

#define CP_ASYNC_16(dst, src) \
    asm volatile("cp.async.cg.shared.global [%0], [%1], 16;" \
        :: "r"(dst), "l"(src) : "memory")
#define CP_ASYNC_COMMIT() asm volatile("cp.async.commit_group;" ::: "memory")
#define CP_ASYNC_WAIT_2() asm volatile("cp.async.wait_group 2;" ::: "memory")

__device__ __forceinline__ void ldmatrix_x4(uint32_t& r0, uint32_t& r1,
                                            uint32_t& r2, uint32_t& r3,
                                            uint32_t addr) {
    asm volatile("ldmatrix.sync.aligned.m8n8.x4.shared.b16 {%0,%1,%2,%3}, [%4];"
                 : "=r"(r0), "=r"(r1), "=r"(r2), "=r"(r3) : "r"(addr));
}

// m16n8k32 s8 IMMA, s32 accumulate
__device__ __forceinline__ void mma_s8(int* d, const uint32_t* a,
                                       uint32_t b0, uint32_t b1) {
    asm volatile(
        "mma.sync.aligned.m16n8k32.row.col.s32.s8.s8.s32 "
        "{%0,%1,%2,%3}, {%4,%5,%6,%7}, {%8,%9}, {%0,%1,%2,%3};"
        : "+r"(d[0]), "+r"(d[1]), "+r"(d[2]), "+r"(d[3])
        : "r"(a[0]), "r"(a[1]), "r"(a[2]), "r"(a[3]), "r"(b0), "r"(b1));
}

// ---------------------------------------------------------------------------
// Conversion kernels
// ---------------------------------------------------------------------------
__device__ __forceinline__ uint32_t pack4_s8(int a, int b, int c, int d) {
    return (uint32_t)(a & 0xFF) | ((uint32_t)(b & 0xFF) << 8) |
           ((uint32_t)(c & 0xFF) << 16) | ((uint32_t)(d & 0xFF) << 24);
}

__global__ void __launch_bounds__(256) convert_x_q_kernel(
    const float4* __restrict__ x, uint32_t* __restrict__ q1,
    uint32_t* __restrict__ q2) {
    int i = blockIdx.x * 256 + threadIdx.x;
    float4 v = x[i];
    float s0 = v.x * 16.f, s1 = v.y * 16.f, s2 = v.z * 16.f, s3 = v.w * 16.f;
    float r0 = fminf(fmaxf(rintf(s0), -127.f), 127.f);
    float r1 = fminf(fmaxf(rintf(s1), -127.f), 127.f);
    float r2 = fminf(fmaxf(rintf(s2), -127.f), 127.f);
    float r3 = fminf(fmaxf(rintf(s3), -127.f), 127.f);
    float t0 = fminf(fmaxf(rintf((s0 - r0) * 256.f), -127.f), 127.f);
    float t1 = fminf(fmaxf(rintf((s1 - r1) * 256.f), -127.f), 127.f);
    float t2 = fminf(fmaxf(rintf((s2 - r2) * 256.f), -127.f), 127.f);
    float t3 = fminf(fmaxf(rintf((s3 - r3) * 256.f), -127.f), 127.f);
    q1[i] = pack4_s8((int)r0, (int)r1, (int)r2, (int)r3);
    q2[i] = pack4_s8((int)t0, (int)t1, (int)t2, (int)t3);
}

__global__ void __launch_bounds__(256) convert_w_s_kernel(
    const float4* __restrict__ w, uint32_t* __restrict__ ws) {
    int i = blockIdx.x * 256 + threadIdx.x;
    float4 v = w[i];
    int s0 = (v.x > 0.f) ? 1 : ((v.x < 0.f) ? -1 : 0);
    int s1 = (v.y > 0.f) ? 1 : ((v.y < 0.f) ? -1 : 0);
    int s2 = (v.z > 0.f) ? 1 : ((v.z < 0.f) ? -1 : 0);
    int s3 = (v.w > 0.f) ? 1 : ((v.w < 0.f) ? -1 : 0);
    ws[i] = pack4_s8(s0, s1, s2, s3);
}

// ---------------------------------------------------------------------------
// GEMM kernel (dual int8 pass, one CTA = 128x256 tile)
// ---------------------------------------------------------------------------
__global__ void __launch_bounds__(THREADS, 1)
bingemm_s8_kernel(const int8_t* __restrict__ q1,
                  const int8_t* __restrict__ q2,
                  const int8_t* __restrict__ ws,
                  const float* __restrict__ bias,
                  float* __restrict__ out) {
    extern __shared__ __align__(1024) char smem[];
    const uint32_t sb = smem_u32(smem);

    const int tid = threadIdx.x;
    const int wid = tid >> 5;
    const int lane = tid & 31;
    const int warp_m = wid & 1;    // 0..1
    const int warp_n = wid >> 1;   // 0..3
    const int m0 = blockIdx.y * BM;
    const int n0 = blockIdx.x * BN;

    // --- cp.async tile loader (row = 128B = 8 x 16B chunks, xor swizzle) ---
    const int ld_row = tid >> 3;   // 0..31
    const int ld_chunk = tid & 7;  // 0..7

    auto load_stage = [&](int stage, int c) {
        const uint32_t sbase = sb + stage * STAGE_BYTES;
        const int8_t* asrc = (c < CHUNKS_PER_PASS) ? q1 : q2;
        const int k0 = (c & (CHUNKS_PER_PASS - 1)) * BK;
        #pragma unroll
        for (int i = 0; i < 4; i++) {
            int row = i * 32 + ld_row;
            uint32_t soff = row * 128 + ((ld_chunk ^ (row & 7)) << 4);
            const int8_t* src = asrc + (size_t)(m0 + row) * KK + k0 + ld_chunk * 16;
            CP_ASYNC_16(sbase + A_OFF + soff, src);
        }
        #pragma unroll
        for (int i = 0; i < 8; i++) {
            int row = i * 32 + ld_row;
            uint32_t soff = row * 128 + ((ld_chunk ^ (row & 7)) << 4);
            const int8_t* src = ws + (size_t)(n0 + row) * KK + k0 + ld_chunk * 16;
            CP_ASYNC_16(sbase + B_OFF + soff, src);
        }
    };

    // prologue: 3 stages in flight
    load_stage(0, 0); CP_ASYNC_COMMIT();
    load_stage(1, 1); CP_ASYNC_COMMIT();
    load_stage(2, 2); CP_ASYNC_COMMIT();

    // --- ldmatrix per-thread address components (byte-identical to bf16 map) ---
    const int mt = lane >> 3;        // matrix index 0..3
    const int lrow = lane & 7;
    // A mats: (m+0,kc0) (m+8,kc0) (m+0,kc1) (m+8,kc1)
    const int a_row = warp_m * 64 + lrow + ((mt & 1) << 3);
    const int a_koff = mt >> 1;      // 16B chunk within k32
    // B mats: (n+0,kc0) (n+0,kc1) (n+8,kc0) (n+8,kc1)
    const int b_row = warp_n * 64 + lrow + ((mt >> 1) << 3);
    const int b_koff = mt & 1;

    // bias, held in regs across both passes
    const int qcol = (lane & 3) * 2;
    float2 bv[8];
    #pragma unroll
    for (int nj = 0; nj < 8; nj++)
        bv[nj] = *reinterpret_cast<const float2*>(
            bias + n0 + warp_n * 64 + nj * 8 + qcol);

    int acc[4][8][4];
    #pragma unroll
    for (int mi = 0; mi < 4; mi++)
        #pragma unroll
        for (int nj = 0; nj < 8; nj++)
            #pragma unroll
            for (int q = 0; q < 4; q++) acc[mi][nj][q] = 0;

    for (int c = 0; c < TOTAL_CHUNKS; c++) {
        // pass boundary: fold S1 into out (exact *2^-4), zero accs.
        // Per-thread only; no barrier needed (same thread re-reads later).
        if (c == CHUNKS_PER_PASS) {
            #pragma unroll
            for (int mi = 0; mi < 4; mi++) {
                int r0 = m0 + warp_m * 64 + mi * 16 + (lane >> 2);
                float* p0 = out + (size_t)r0 * NN + n0 + warp_n * 64 + qcol;
                float* p1 = p0 + 8 * NN;
                #pragma unroll
                for (int nj = 0; nj < 8; nj++) {
                    float2 v0, v1;
                    v0.x = (float)acc[mi][nj][0] * 0.0625f + bv[nj].x;
                    v0.y = (float)acc[mi][nj][1] * 0.0625f + bv[nj].y;
                    v1.x = (float)acc[mi][nj][2] * 0.0625f + bv[nj].x;
                    v1.y = (float)acc[mi][nj][3] * 0.0625f + bv[nj].y;
                    *reinterpret_cast<float2*>(p0 + nj * 8) = v0;
                    *reinterpret_cast<float2*>(p1 + nj * 8) = v1;
                    acc[mi][nj][0] = 0; acc[mi][nj][1] = 0;
                    acc[mi][nj][2] = 0; acc[mi][nj][3] = 0;
                }
            }
        }

        CP_ASYNC_WAIT_2();
        __syncthreads();
        if (c + 3 < TOTAL_CHUNKS) load_stage((c + 3) & (STAGES - 1), c + 3);
        CP_ASYNC_COMMIT();

        const uint32_t sbase = sb + (c & (STAGES - 1)) * STAGE_BYTES;

        #pragma unroll
        for (int ks = 0; ks < 4; ks++) {          // 4 x k32 per 128B row
            uint32_t a[4][4];
            #pragma unroll
            for (int mi = 0; mi < 4; mi++) {
                int row = a_row + mi * 16;
                int kch = ks * 2 + a_koff;
                uint32_t off = row * 128 + ((kch ^ (row & 7)) << 4);
                ldmatrix_x4(a[mi][0], a[mi][1], a[mi][2], a[mi][3],
                            sbase + A_OFF + off);
            }
            #pragma unroll
            for (int nj2 = 0; nj2 < 4; nj2++) {
                int row = b_row + nj2 * 16;
                int kch = ks * 2 + b_koff;
                uint32_t off = row * 128 + ((kch ^ (row & 7)) << 4);
                uint32_t b0, b1, b2, b3;
                ldmatrix_x4(b0, b1, b2, b3, sbase + B_OFF + off);
                #pragma unroll
                for (int mi = 0; mi < 4; mi++) {
                    mma_s8(acc[mi][nj2 * 2 + 0], a[mi], b0, b1);
                    mma_s8(acc[mi][nj2 * 2 + 1], a[mi], b2, b3);
                }
            }
        }
        __syncthreads();
    }

    // --- final epilogue: out += S2 / 4096 ---
    constexpr float K2 = 1.f / 4096.f;
    #pragma unroll
    for (int mi = 0; mi < 4; mi++) {
        int r0 = m0 + warp_m * 64 + mi * 16 + (lane >> 2);
        float* p0 = out + (size_t)r0 * NN + n0 + warp_n * 64 + qcol;
        float* p1 = p0 + 8 * NN;
        #pragma unroll
        for (int nj = 0; nj < 8; nj++) {
            float2 v0 = *reinterpret_cast<float2*>(p0 + nj * 8);
            float2 v1 = *reinterpret_cast<float2*>(p1 + nj * 8);
            v0.x += (float)acc[mi][nj][0] * K2;
            v0.y += (float)acc[mi][nj][1] * K2;
            v1.x += (float)acc[mi][nj][2] * K2;
            v1.y += (float)acc[mi][nj][3] * K2;
            *reinterpret_cast<float2*>(p0 + nj * 8) = v0;
            *reinterpret_cast<float2*>(p1 + nj * 8) = v1;
        }
    }
}

// ---------------------------------------------------------------------------
// Host launch
// ---------------------------------------------------------------------------
extern "C" void kernel_launch(void* const* d_in, const int* in_sizes, int n_in,
                              void* d_out, int out_size) {
    const float* x    = (const float*)d_in[0];
    const float* w    = (const float*)d_in[1];
    const float* bias = (const float*)d_in[2];
    float* out = (float*)d_out;

    void *p_q1 = nullptr, *p_q2 = nullptr, *p_ws = nullptr;
    cudaGetSymbolAddress(&p_q1, g_q1);
    cudaGetSymbolAddress(&p_q2, g_q2);
    cudaGetSymbolAddress(&p_ws, g_ws);

    const int n4 = MM * KK / 4;
    convert_x_q_kernel<<<n4 / 256, 256>>>((const float4*)x,
                                          (uint32_t*)p_q1, (uint32_t*)p_q2);
    convert_w_s_kernel<<<n4 / 256, 256>>>((const float4*)w, (uint32_t*)p_ws);

    static bool attr_set = false;
    if (!attr_set) {
        cudaFuncSetAttribute(bingemm_s8_kernel,
                             cudaFuncAttributeMaxDynamicSharedMemorySize, SMEM_TOTAL);
        attr_set = true;
    }

    dim3 grid(NN / BN, MM / BM);  // (16, 32)
    bingemm_s8_kernel<<<grid, THREADS, SMEM_TOTAL>>>(
        (const int8_t*)p_q1, (const int8_t*)p_q2, (const int8_t*)p_ws,
        bias, out);
}

// round 5
// speedup vs baseline: 3.0884x; 3.0884x over previous
#include <cuda_runtime.h>
#include <cuda_bf16.h>
#include <cstdint>

// ============================================================================
// out[M,N] = X[M,K] @ sign(W)[N,K]^T + bias[N],  M=N=K=4096, fp32.
// sm_103 plain PTX target => legacy mma.sync bf16 path (tcgen05 unavailable;
// legacy s8 IMMA measured 3x SLOWER on sm_103 - do not use).
// Numerics: X -> bf16 hi + lo (two HMMA passes, fp32 acc) => rel_err ~6e-6.
// R5: 512 threads / 16 warps (warp tile 64x32) for 4 warps/SMSP latency
// hiding; JIT A-fragment loads to keep regs ~<=120.
// ============================================================================

static constexpr int MM = 4096;
static constexpr int NN = 4096;
static constexpr int KK = 4096;

static constexpr int BM = 128;
static constexpr int BN = 256;
static constexpr int BK = 64;            // 64 bf16 = 128B row
static constexpr int STAGES = 3;
static constexpr int CHUNKS = KK / BK;   // 64
static constexpr int THREADS = 512;      // 16 warps: 2 (M) x 8 (N), warp 64x32

// SMEM stage layout (bytes)
static constexpr int XH_BYTES = BM * 128;          // 16384
static constexpr int XL_BYTES = BM * 128;          // 16384
static constexpr int B_BYTES  = BN * 128;          // 32768
static constexpr int XH_OFF = 0;
static constexpr int XL_OFF = XH_BYTES;
static constexpr int B_OFF  = XH_BYTES + XL_BYTES;
static constexpr int STAGE_BYTES = XH_BYTES + XL_BYTES + B_BYTES;  // 65536
static constexpr int SMEM_TOTAL = STAGES * STAGE_BYTES;            // 196608

// ---------------------------------------------------------------------------
// Scratch (allocation-free)
// ---------------------------------------------------------------------------
__device__ __align__(1024) __nv_bfloat16 g_xh[(size_t)MM * KK];
__device__ __align__(1024) __nv_bfloat16 g_xl[(size_t)MM * KK];
__device__ __align__(1024) __nv_bfloat16 g_wb[(size_t)NN * KK];

// ---------------------------------------------------------------------------
// helpers
// ---------------------------------------------------------------------------
__device__ __forceinline__ uint32_t smem_u32(const void* p) {
    uint32_t a;
    asm("{ .reg .u64 t; cvta.to.shared.u64 t, %1; cvt.u32.u64 %0, t; }"
        : "=r"(a) : "l"(p));
    return a;
}

#define CP_ASYNC_16(dst, src) \
    asm volatile("cp.async.cg.shared.global [%0], [%1], 16;" \
        :: "r"(dst), "l"(src) : "memory")
#define CP_ASYNC_COMMIT() asm volatile("cp.async.commit_group;" ::: "memory")
#define CP_ASYNC_WAIT_1() asm volatile("cp.async.wait_group 1;" ::: "memory")

__device__ __forceinline__ void ldmatrix_x4(uint32_t& r0, uint32_t& r1,
                                            uint32_t& r2, uint32_t& r3,
                                            uint32_t addr) {
    asm volatile("ldmatrix.sync.aligned.m8n8.x4.shared.b16 {%0,%1,%2,%3}, [%4];"
                 : "=r"(r0), "=r"(r1), "=r"(r2), "=r"(r3) : "r"(addr));
}

__device__ __forceinline__ void mma_bf16(float* d, const uint32_t* a,
                                         uint32_t b0, uint32_t b1) {
    asm volatile(
        "mma.sync.aligned.m16n8k16.row.col.f32.bf16.bf16.f32 "
        "{%0,%1,%2,%3}, {%4,%5,%6,%7}, {%8,%9}, {%0,%1,%2,%3};"
        : "+f"(d[0]), "+f"(d[1]), "+f"(d[2]), "+f"(d[3])
        : "r"(a[0]), "r"(a[1]), "r"(a[2]), "r"(a[3]), "r"(b0), "r"(b1));
}

// ---------------------------------------------------------------------------
// Conversion kernels
// ---------------------------------------------------------------------------
__device__ __forceinline__ uint32_t pack2(__nv_bfloat16 a, __nv_bfloat16 b) {
    return ((uint32_t)__bfloat16_as_ushort(b) << 16) | (uint32_t)__bfloat16_as_ushort(a);
}

__global__ void __launch_bounds__(256) convert_x_kernel(
    const float4* __restrict__ x, uint2* __restrict__ xh, uint2* __restrict__ xl) {
    int i = blockIdx.x * 256 + threadIdx.x;
    float4 v = x[i];
    __nv_bfloat16 h0 = __float2bfloat16(v.x);
    __nv_bfloat16 h1 = __float2bfloat16(v.y);
    __nv_bfloat16 h2 = __float2bfloat16(v.z);
    __nv_bfloat16 h3 = __float2bfloat16(v.w);
    __nv_bfloat16 l0 = __float2bfloat16(v.x - __bfloat162float(h0));
    __nv_bfloat16 l1 = __float2bfloat16(v.y - __bfloat162float(h1));
    __nv_bfloat16 l2 = __float2bfloat16(v.z - __bfloat162float(h2));
    __nv_bfloat16 l3 = __float2bfloat16(v.w - __bfloat162float(h3));
    uint2 ph; ph.x = pack2(h0, h1); ph.y = pack2(h2, h3);
    uint2 pl; pl.x = pack2(l0, l1); pl.y = pack2(l2, l3);
    xh[i] = ph;
    xl[i] = pl;
}

__global__ void __launch_bounds__(256) convert_w_kernel(
    const float4* __restrict__ w, uint2* __restrict__ wb) {
    int i = blockIdx.x * 256 + threadIdx.x;
    float4 v = w[i];
    float s0 = (v.x > 0.f) ? 1.f : ((v.x < 0.f) ? -1.f : 0.f);
    float s1 = (v.y > 0.f) ? 1.f : ((v.y < 0.f) ? -1.f : 0.f);
    float s2 = (v.z > 0.f) ? 1.f : ((v.z < 0.f) ? -1.f : 0.f);
    float s3 = (v.w > 0.f) ? 1.f : ((v.w < 0.f) ? -1.f : 0.f);
    uint2 p;
    p.x = pack2(__float2bfloat16(s0), __float2bfloat16(s1));
    p.y = pack2(__float2bfloat16(s2), __float2bfloat16(s3));
    wb[i] = p;
}

// ---------------------------------------------------------------------------
// GEMM kernel
// ---------------------------------------------------------------------------
__global__ void __launch_bounds__(THREADS, 1)
bingemm_kernel(const __nv_bfloat16* __restrict__ xh,
               const __nv_bfloat16* __restrict__ xl,
               const __nv_bfloat16* __restrict__ wb,
               const float* __restrict__ bias,
               float* __restrict__ out) {
    extern __shared__ __align__(1024) char smem[];
    const uint32_t sb = smem_u32(smem);

    const int tid = threadIdx.x;
    const int wid = tid >> 5;
    const int lane = tid & 31;
    const int warp_m = wid & 1;    // 0..1  -> 64 rows
    const int warp_n = wid >> 1;   // 0..7  -> 32 cols
    const int m0 = blockIdx.y * BM;
    const int n0 = blockIdx.x * BN;

    // --- cp.async tile loader: 512 threads, row=128B=8x16B chunks, xor swizzle
    const int ld_row = tid >> 3;   // 0..63
    const int ld_chunk = tid & 7;  // 0..7

    auto load_stage = [&](int stage, int c) {
        const uint32_t sbase = sb + stage * STAGE_BYTES;
        const int k0 = c * BK;
        #pragma unroll
        for (int i = 0; i < 2; i++) {
            int row = i * 64 + ld_row;
            uint32_t soff = row * 128 + ((ld_chunk ^ (row & 7)) << 4);
            CP_ASYNC_16(sbase + XH_OFF + soff,
                        xh + (size_t)(m0 + row) * KK + k0 + ld_chunk * 8);
        }
        #pragma unroll
        for (int i = 0; i < 2; i++) {
            int row = i * 64 + ld_row;
            uint32_t soff = row * 128 + ((ld_chunk ^ (row & 7)) << 4);
            CP_ASYNC_16(sbase + XL_OFF + soff,
                        xl + (size_t)(m0 + row) * KK + k0 + ld_chunk * 8);
        }
        #pragma unroll
        for (int i = 0; i < 4; i++) {
            int row = i * 64 + ld_row;
            uint32_t soff = row * 128 + ((ld_chunk ^ (row & 7)) << 4);
            CP_ASYNC_16(sbase + B_OFF + soff,
                        wb + (size_t)(n0 + row) * KK + k0 + ld_chunk * 8);
        }
    };

    // prologue
    load_stage(0, 0); CP_ASYNC_COMMIT();
    load_stage(1, 1); CP_ASYNC_COMMIT();

    // --- ldmatrix per-thread address components ---
    const int mt = lane >> 3;            // matrix index 0..3
    const int lrow = lane & 7;
    // A mats: (m+0,kc0) (m+8,kc0) (m+0,kc1) (m+8,kc1)
    const int a_row = warp_m * 64 + lrow + ((mt & 1) << 3);   // + mi*16
    const int a_koff = mt >> 1;
    // B mats: (n+0,kc0) (n+0,kc1) (n+8,kc0) (n+8,kc1)
    const int b_row = warp_n * 32 + lrow + ((mt >> 1) << 3);  // + nj2*16
    const int b_koff = mt & 1;

    float acc[4][4][4];                  // mi, nj(4 x n8), quad
    #pragma unroll
    for (int mi = 0; mi < 4; mi++)
        #pragma unroll
        for (int nj = 0; nj < 4; nj++)
            #pragma unroll
            for (int q = 0; q < 4; q++) acc[mi][nj][q] = 0.f;

    for (int c = 0; c < CHUNKS; c++) {
        CP_ASYNC_WAIT_1();
        __syncthreads();
        if (c + 2 < CHUNKS) load_stage((c + 2) % STAGES, c + 2);
        CP_ASYNC_COMMIT();

        const uint32_t sbase = sb + (c % STAGES) * STAGE_BYTES;

        #pragma unroll
        for (int ks = 0; ks < 4; ks++) {
            // B fragments for this warp's 32 columns (2 x ldmatrix.x4)
            uint32_t b[2][4];
            #pragma unroll
            for (int nj2 = 0; nj2 < 2; nj2++) {
                int row = b_row + nj2 * 16;
                int kch = ks * 2 + b_koff;
                uint32_t off = row * 128 + ((kch ^ (row & 7)) << 4);
                ldmatrix_x4(b[nj2][0], b[nj2][1], b[nj2][2], b[nj2][3],
                            sbase + B_OFF + off);
            }
            // A fragments just-in-time per 16-row slice
            #pragma unroll
            for (int mi = 0; mi < 4; mi++) {
                int row = a_row + mi * 16;
                int kch = ks * 2 + a_koff;
                uint32_t off = row * 128 + ((kch ^ (row & 7)) << 4);
                uint32_t ah[4], al[4];
                ldmatrix_x4(ah[0], ah[1], ah[2], ah[3], sbase + XH_OFF + off);
                ldmatrix_x4(al[0], al[1], al[2], al[3], sbase + XL_OFF + off);
                #pragma unroll
                for (int nj2 = 0; nj2 < 2; nj2++) {
                    mma_bf16(acc[mi][nj2 * 2 + 0], ah, b[nj2][0], b[nj2][1]);
                    mma_bf16(acc[mi][nj2 * 2 + 1], ah, b[nj2][2], b[nj2][3]);
                    mma_bf16(acc[mi][nj2 * 2 + 0], al, b[nj2][0], b[nj2][1]);
                    mma_bf16(acc[mi][nj2 * 2 + 1], al, b[nj2][2], b[nj2][3]);
                }
            }
        }
        __syncthreads();
    }

    // --- epilogue: += bias, write fp32 ---
    const int qcol = (lane & 3) * 2;
    float2 bv[4];
    #pragma unroll
    for (int nj = 0; nj < 4; nj++)
        bv[nj] = *reinterpret_cast<const float2*>(
            bias + n0 + warp_n * 32 + nj * 8 + qcol);

    #pragma unroll
    for (int mi = 0; mi < 4; mi++) {
        int r0 = m0 + warp_m * 64 + mi * 16 + (lane >> 2);
        float* p0 = out + (size_t)r0 * NN + n0 + warp_n * 32 + qcol;
        float* p1 = p0 + 8 * NN;
        #pragma unroll
        for (int nj = 0; nj < 4; nj++) {
            float2 v0, v1;
            v0.x = acc[mi][nj][0] + bv[nj].x;
            v0.y = acc[mi][nj][1] + bv[nj].y;
            v1.x = acc[mi][nj][2] + bv[nj].x;
            v1.y = acc[mi][nj][3] + bv[nj].y;
            *reinterpret_cast<float2*>(p0 + nj * 8) = v0;
            *reinterpret_cast<float2*>(p1 + nj * 8) = v1;
        }
    }
}

// ---------------------------------------------------------------------------
// Host launch
// ---------------------------------------------------------------------------
extern "C" void kernel_launch(void* const* d_in, const int* in_sizes, int n_in,
                              void* d_out, int out_size) {
    const float* x    = (const float*)d_in[0];
    const float* w    = (const float*)d_in[1];
    const float* bias = (const float*)d_in[2];
    float* out = (float*)d_out;

    void *p_xh = nullptr, *p_xl = nullptr, *p_wb = nullptr;
    cudaGetSymbolAddress(&p_xh, g_xh);
    cudaGetSymbolAddress(&p_xl, g_xl);
    cudaGetSymbolAddress(&p_wb, g_wb);

    const int n4 = MM * KK / 4;
    convert_x_kernel<<<n4 / 256, 256>>>((const float4*)x, (uint2*)p_xh, (uint2*)p_xl);
    convert_w_kernel<<<n4 / 256, 256>>>((const float4*)w, (uint2*)p_wb);

    static bool attr_set = false;
    if (!attr_set) {
        cudaFuncSetAttribute(bingemm_kernel,
                             cudaFuncAttributeMaxDynamicSharedMemorySize, SMEM_TOTAL);
        attr_set = true;
    }

    dim3 grid(NN / BN, MM / BM);  // (16, 32)
    bingemm_kernel<<<grid, THREADS, SMEM_TOTAL>>>(
        (const __nv_bfloat16*)p_xh, (const __nv_bfloat16*)p_xl,
        (const __nv_bfloat16*)p_wb, bias, out);
}

// round 6
// speedup vs baseline: 5.3464x; 1.7311x over previous
#include <cuda_runtime.h>
#include <cuda_fp16.h>
#include <cstdint>

// ============================================================================
// out[M,N] = X[M,K] @ sign(W)[N,K]^T + bias[N],  M=N=K=4096, fp32.
// sm_103 plain PTX target => legacy mma.sync path only.
//   - tcgen05: not emittable (harness compiles PTX for sm_103, no 'a')
//   - legacy s8 IMMA: measured 3x SLOWER than bf16 HMMA on sm_103 (R4)
//   - dual bf16 hi/lo: 711us, HMMA-throughput-bound (R3/R5)
// R6: SINGLE fp16 pass. sign(W) in {-1,0,1} is exact in fp16, so the only
// error is fp16(x) rounding: rel err ~2.8e-4 << 1e-3 gate. Tensor work halves.
// ============================================================================

static constexpr int MM = 4096;
static constexpr int NN = 4096;
static constexpr int KK = 4096;

static constexpr int BM = 128;
static constexpr int BN = 256;
static constexpr int BK = 64;            // 64 fp16 = 128B row
static constexpr int STAGES = 4;
static constexpr int CHUNKS = KK / BK;   // 64
static constexpr int THREADS = 256;      // 8 warps: 2 (M) x 4 (N), warp 64x64

// SMEM stage layout (bytes)
static constexpr int A_BYTES = BM * 128;           // 16384
static constexpr int B_BYTES = BN * 128;           // 32768
static constexpr int A_OFF = 0;
static constexpr int B_OFF = A_BYTES;
static constexpr int STAGE_BYTES = A_BYTES + B_BYTES;   // 49152
static constexpr int SMEM_TOTAL = STAGES * STAGE_BYTES; // 196608

// ---------------------------------------------------------------------------
// Scratch (allocation-free)
// ---------------------------------------------------------------------------
__device__ __align__(1024) __half g_xa[(size_t)MM * KK];
__device__ __align__(1024) __half g_wb[(size_t)NN * KK];

// ---------------------------------------------------------------------------
// helpers
// ---------------------------------------------------------------------------
__device__ __forceinline__ uint32_t smem_u32(const void* p) {
    uint32_t a;
    asm("{ .reg .u64 t; cvta.to.shared.u64 t, %1; cvt.u32.u64 %0, t; }"
        : "=r"(a) : "l"(p));
    return a;
}

#define CP_ASYNC_16(dst, src) \
    asm volatile("cp.async.cg.shared.global [%0], [%1], 16;" \
        :: "r"(dst), "l"(src) : "memory")
#define CP_ASYNC_COMMIT() asm volatile("cp.async.commit_group;" ::: "memory")
#define CP_ASYNC_WAIT_2() asm volatile("cp.async.wait_group 2;" ::: "memory")

__device__ __forceinline__ void ldmatrix_x4(uint32_t& r0, uint32_t& r1,
                                            uint32_t& r2, uint32_t& r3,
                                            uint32_t addr) {
    asm volatile("ldmatrix.sync.aligned.m8n8.x4.shared.b16 {%0,%1,%2,%3}, [%4];"
                 : "=r"(r0), "=r"(r1), "=r"(r2), "=r"(r3) : "r"(addr));
}

__device__ __forceinline__ void mma_f16(float* d, const uint32_t* a,
                                        uint32_t b0, uint32_t b1) {
    asm volatile(
        "mma.sync.aligned.m16n8k16.row.col.f32.f16.f16.f32 "
        "{%0,%1,%2,%3}, {%4,%5,%6,%7}, {%8,%9}, {%0,%1,%2,%3};"
        : "+f"(d[0]), "+f"(d[1]), "+f"(d[2]), "+f"(d[3])
        : "r"(a[0]), "r"(a[1]), "r"(a[2]), "r"(a[3]), "r"(b0), "r"(b1));
}

// ---------------------------------------------------------------------------
// Conversion kernels
// ---------------------------------------------------------------------------
__global__ void __launch_bounds__(256) convert_x_kernel(
    const float4* __restrict__ x, uint2* __restrict__ xa) {
    int i = blockIdx.x * 256 + threadIdx.x;
    float4 v = x[i];
    __half2 p01 = __floats2half2_rn(v.x, v.y);
    __half2 p23 = __floats2half2_rn(v.z, v.w);
    uint2 p;
    p.x = *reinterpret_cast<uint32_t*>(&p01);
    p.y = *reinterpret_cast<uint32_t*>(&p23);
    xa[i] = p;
}

__global__ void __launch_bounds__(256) convert_w_kernel(
    const float4* __restrict__ w, uint2* __restrict__ wb) {
    int i = blockIdx.x * 256 + threadIdx.x;
    float4 v = w[i];
    float s0 = (v.x > 0.f) ? 1.f : ((v.x < 0.f) ? -1.f : 0.f);
    float s1 = (v.y > 0.f) ? 1.f : ((v.y < 0.f) ? -1.f : 0.f);
    float s2 = (v.z > 0.f) ? 1.f : ((v.z < 0.f) ? -1.f : 0.f);
    float s3 = (v.w > 0.f) ? 1.f : ((v.w < 0.f) ? -1.f : 0.f);
    __half2 p01 = __floats2half2_rn(s0, s1);
    __half2 p23 = __floats2half2_rn(s2, s3);
    uint2 p;
    p.x = *reinterpret_cast<uint32_t*>(&p01);
    p.y = *reinterpret_cast<uint32_t*>(&p23);
    wb[i] = p;
}

// ---------------------------------------------------------------------------
// GEMM kernel (single fp16 pass)
// ---------------------------------------------------------------------------
__global__ void __launch_bounds__(THREADS, 1)
bingemm_kernel(const __half* __restrict__ xa,
               const __half* __restrict__ wb,
               const float* __restrict__ bias,
               float* __restrict__ out) {
    extern __shared__ __align__(1024) char smem[];
    const uint32_t sb = smem_u32(smem);

    const int tid = threadIdx.x;
    const int wid = tid >> 5;
    const int lane = tid & 31;
    const int warp_m = wid & 1;    // 0..1 -> 64 rows
    const int warp_n = wid >> 1;   // 0..3 -> 64 cols
    const int m0 = blockIdx.y * BM;
    const int n0 = blockIdx.x * BN;

    // --- cp.async tile loader (row = 128B = 8 x 16B chunks, xor swizzle) ---
    const int ld_row = tid >> 3;   // 0..31
    const int ld_chunk = tid & 7;  // 0..7

    auto load_stage = [&](int stage, int c) {
        const uint32_t sbase = sb + stage * STAGE_BYTES;
        const int k0 = c * BK;
        #pragma unroll
        for (int i = 0; i < 4; i++) {
            int row = i * 32 + ld_row;
            uint32_t soff = row * 128 + ((ld_chunk ^ (row & 7)) << 4);
            CP_ASYNC_16(sbase + A_OFF + soff,
                        xa + (size_t)(m0 + row) * KK + k0 + ld_chunk * 8);
        }
        #pragma unroll
        for (int i = 0; i < 8; i++) {
            int row = i * 32 + ld_row;
            uint32_t soff = row * 128 + ((ld_chunk ^ (row & 7)) << 4);
            CP_ASYNC_16(sbase + B_OFF + soff,
                        wb + (size_t)(n0 + row) * KK + k0 + ld_chunk * 8);
        }
    };

    // prologue: 3 stages in flight
    load_stage(0, 0); CP_ASYNC_COMMIT();
    load_stage(1, 1); CP_ASYNC_COMMIT();
    load_stage(2, 2); CP_ASYNC_COMMIT();

    // --- ldmatrix per-thread address components ---
    const int mt = lane >> 3;            // matrix index 0..3
    const int lrow = lane & 7;
    // A mats: (m+0,kc0) (m+8,kc0) (m+0,kc1) (m+8,kc1)
    const int a_row = warp_m * 64 + lrow + ((mt & 1) << 3);   // + mi*16
    const int a_koff = mt >> 1;
    // B mats: (n+0,kc0) (n+0,kc1) (n+8,kc0) (n+8,kc1)
    const int b_row = warp_n * 64 + lrow + ((mt >> 1) << 3);  // + nj2*16
    const int b_koff = mt & 1;

    float acc[4][8][4];
    #pragma unroll
    for (int mi = 0; mi < 4; mi++)
        #pragma unroll
        for (int nj = 0; nj < 8; nj++)
            #pragma unroll
            for (int q = 0; q < 4; q++) acc[mi][nj][q] = 0.f;

    for (int c = 0; c < CHUNKS; c++) {
        CP_ASYNC_WAIT_2();
        __syncthreads();
        if (c + 3 < CHUNKS) load_stage((c + 3) & (STAGES - 1), c + 3);
        CP_ASYNC_COMMIT();

        const uint32_t sbase = sb + (c & (STAGES - 1)) * STAGE_BYTES;

        #pragma unroll
        for (int ks = 0; ks < 4; ks++) {
            uint32_t a[4][4];
            #pragma unroll
            for (int mi = 0; mi < 4; mi++) {
                int row = a_row + mi * 16;
                int kch = ks * 2 + a_koff;
                uint32_t off = row * 128 + ((kch ^ (row & 7)) << 4);
                ldmatrix_x4(a[mi][0], a[mi][1], a[mi][2], a[mi][3],
                            sbase + A_OFF + off);
            }
            #pragma unroll
            for (int nj2 = 0; nj2 < 4; nj2++) {
                int row = b_row + nj2 * 16;
                int kch = ks * 2 + b_koff;
                uint32_t off = row * 128 + ((kch ^ (row & 7)) << 4);
                uint32_t b0, b1, b2, b3;
                ldmatrix_x4(b0, b1, b2, b3, sbase + B_OFF + off);
                #pragma unroll
                for (int mi = 0; mi < 4; mi++) {
                    mma_f16(acc[mi][nj2 * 2 + 0], a[mi], b0, b1);
                    mma_f16(acc[mi][nj2 * 2 + 1], a[mi], b2, b3);
                }
            }
        }
        __syncthreads();
    }

    // --- epilogue: += bias, write fp32 ---
    const int qcol = (lane & 3) * 2;
    float2 bv[8];
    #pragma unroll
    for (int nj = 0; nj < 8; nj++)
        bv[nj] = *reinterpret_cast<const float2*>(
            bias + n0 + warp_n * 64 + nj * 8 + qcol);

    #pragma unroll
    for (int mi = 0; mi < 4; mi++) {
        int r0 = m0 + warp_m * 64 + mi * 16 + (lane >> 2);
        float* p0 = out + (size_t)r0 * NN + n0 + warp_n * 64 + qcol;
        float* p1 = p0 + 8 * NN;
        #pragma unroll
        for (int nj = 0; nj < 8; nj++) {
            float2 v0, v1;
            v0.x = acc[mi][nj][0] + bv[nj].x;
            v0.y = acc[mi][nj][1] + bv[nj].y;
            v1.x = acc[mi][nj][2] + bv[nj].x;
            v1.y = acc[mi][nj][3] + bv[nj].y;
            *reinterpret_cast<float2*>(p0 + nj * 8) = v0;
            *reinterpret_cast<float2*>(p1 + nj * 8) = v1;
        }
    }
}

// ---------------------------------------------------------------------------
// Host launch
// ---------------------------------------------------------------------------
extern "C" void kernel_launch(void* const* d_in, const int* in_sizes, int n_in,
                              void* d_out, int out_size) {
    const float* x    = (const float*)d_in[0];
    const float* w    = (const float*)d_in[1];
    const float* bias = (const float*)d_in[2];
    float* out = (float*)d_out;

    void *p_xa = nullptr, *p_wb = nullptr;
    cudaGetSymbolAddress(&p_xa, g_xa);
    cudaGetSymbolAddress(&p_wb, g_wb);

    const int n4 = MM * KK / 4;
    convert_x_kernel<<<n4 / 256, 256>>>((const float4*)x, (uint2*)p_xa);
    convert_w_kernel<<<n4 / 256, 256>>>((const float4*)w, (uint2*)p_wb);

    static bool attr_set = false;
    if (!attr_set) {
        cudaFuncSetAttribute(bingemm_kernel,
                             cudaFuncAttributeMaxDynamicSharedMemorySize, SMEM_TOTAL);
        attr_set = true;
    }

    dim3 grid(NN / BN, MM / BM);  // (16, 32)
    bingemm_kernel<<<grid, THREADS, SMEM_TOTAL>>>(
        (const __half*)p_xa, (const __half*)p_wb, bias, out);
}

// round 7
// speedup vs baseline: 6.1752x; 1.1550x over previous
#include <cuda_runtime.h>
#include <cuda_fp16.h>
#include <cstdint>

// ============================================================================
// out[M,N] = X[M,K] @ sign(W)[N,K]^T + bias[N],  M=N=K=4096, fp32.
// sm_103 plain PTX target => legacy mma.sync path only.
//   - tcgen05: not emittable (harness PTX target sm_103, no 'a')
//   - legacy s8 IMMA: 3x SLOWER than HMMA on sm_103 (R4)
//   - single fp16 pass: rel_err 2.1e-4, 411us (R6)
// R7: BN 256->128, 2 CTAs/SM (96KB smem each) for cross-CTA overlap of
// barrier bubbles + smaller wave-tail quantization (1024 CTAs, 6.9 waves).
// ============================================================================

static constexpr int MM = 4096;
static constexpr int NN = 4096;
static constexpr int KK = 4096;

static constexpr int BM = 128;
static constexpr int BN = 128;
static constexpr int BK = 64;            // 64 fp16 = 128B row
static constexpr int STAGES = 3;
static constexpr int CHUNKS = KK / BK;   // 64
static constexpr int THREADS = 256;      // 8 warps: 2 (M) x 4 (N), warp 64x32

// SMEM stage layout (bytes)
static constexpr int A_BYTES = BM * 128;           // 16384
static constexpr int B_BYTES = BN * 128;           // 16384
static constexpr int A_OFF = 0;
static constexpr int B_OFF = A_BYTES;
static constexpr int STAGE_BYTES = A_BYTES + B_BYTES;   // 32768
static constexpr int SMEM_TOTAL = STAGES * STAGE_BYTES; // 98304

// ---------------------------------------------------------------------------
// Scratch (allocation-free)
// ---------------------------------------------------------------------------
__device__ __align__(1024) __half g_xa[(size_t)MM * KK];
__device__ __align__(1024) __half g_wb[(size_t)NN * KK];

// ---------------------------------------------------------------------------
// helpers
// ---------------------------------------------------------------------------
__device__ __forceinline__ uint32_t smem_u32(const void* p) {
    uint32_t a;
    asm("{ .reg .u64 t; cvta.to.shared.u64 t, %1; cvt.u32.u64 %0, t; }"
        : "=r"(a) : "l"(p));
    return a;
}

#define CP_ASYNC_16(dst, src) \
    asm volatile("cp.async.cg.shared.global [%0], [%1], 16;" \
        :: "r"(dst), "l"(src) : "memory")
#define CP_ASYNC_COMMIT() asm volatile("cp.async.commit_group;" ::: "memory")
#define CP_ASYNC_WAIT_1() asm volatile("cp.async.wait_group 1;" ::: "memory")

__device__ __forceinline__ void ldmatrix_x4(uint32_t& r0, uint32_t& r1,
                                            uint32_t& r2, uint32_t& r3,
                                            uint32_t addr) {
    asm volatile("ldmatrix.sync.aligned.m8n8.x4.shared.b16 {%0,%1,%2,%3}, [%4];"
                 : "=r"(r0), "=r"(r1), "=r"(r2), "=r"(r3) : "r"(addr));
}

__device__ __forceinline__ void mma_f16(float* d, const uint32_t* a,
                                        uint32_t b0, uint32_t b1) {
    asm volatile(
        "mma.sync.aligned.m16n8k16.row.col.f32.f16.f16.f32 "
        "{%0,%1,%2,%3}, {%4,%5,%6,%7}, {%8,%9}, {%0,%1,%2,%3};"
        : "+f"(d[0]), "+f"(d[1]), "+f"(d[2]), "+f"(d[3])
        : "r"(a[0]), "r"(a[1]), "r"(a[2]), "r"(a[3]), "r"(b0), "r"(b1));
}

// ---------------------------------------------------------------------------
// Conversion kernels
// ---------------------------------------------------------------------------
__global__ void __launch_bounds__(256) convert_x_kernel(
    const float4* __restrict__ x, uint2* __restrict__ xa) {
    int i = blockIdx.x * 256 + threadIdx.x;
    float4 v = x[i];
    __half2 p01 = __floats2half2_rn(v.x, v.y);
    __half2 p23 = __floats2half2_rn(v.z, v.w);
    uint2 p;
    p.x = *reinterpret_cast<uint32_t*>(&p01);
    p.y = *reinterpret_cast<uint32_t*>(&p23);
    xa[i] = p;
}

__global__ void __launch_bounds__(256) convert_w_kernel(
    const float4* __restrict__ w, uint2* __restrict__ wb) {
    int i = blockIdx.x * 256 + threadIdx.x;
    float4 v = w[i];
    float s0 = (v.x > 0.f) ? 1.f : ((v.x < 0.f) ? -1.f : 0.f);
    float s1 = (v.y > 0.f) ? 1.f : ((v.y < 0.f) ? -1.f : 0.f);
    float s2 = (v.z > 0.f) ? 1.f : ((v.z < 0.f) ? -1.f : 0.f);
    float s3 = (v.w > 0.f) ? 1.f : ((v.w < 0.f) ? -1.f : 0.f);
    __half2 p01 = __floats2half2_rn(s0, s1);
    __half2 p23 = __floats2half2_rn(s2, s3);
    uint2 p;
    p.x = *reinterpret_cast<uint32_t*>(&p01);
    p.y = *reinterpret_cast<uint32_t*>(&p23);
    wb[i] = p;
}

// ---------------------------------------------------------------------------
// GEMM kernel (single fp16 pass, 2 CTAs/SM)
// ---------------------------------------------------------------------------
__global__ void __launch_bounds__(THREADS, 2)
bingemm_kernel(const __half* __restrict__ xa,
               const __half* __restrict__ wb,
               const float* __restrict__ bias,
               float* __restrict__ out) {
    extern __shared__ __align__(1024) char smem[];
    const uint32_t sb = smem_u32(smem);

    const int tid = threadIdx.x;
    const int wid = tid >> 5;
    const int lane = tid & 31;
    const int warp_m = wid & 1;    // 0..1 -> 64 rows
    const int warp_n = wid >> 1;   // 0..3 -> 32 cols
    const int m0 = blockIdx.y * BM;
    const int n0 = blockIdx.x * BN;

    // --- cp.async tile loader (row = 128B = 8 x 16B chunks, xor swizzle) ---
    const int ld_row = tid >> 3;   // 0..31
    const int ld_chunk = tid & 7;  // 0..7

    auto load_stage = [&](int stage, int c) {
        const uint32_t sbase = sb + stage * STAGE_BYTES;
        const int k0 = c * BK;
        #pragma unroll
        for (int i = 0; i < 4; i++) {
            int row = i * 32 + ld_row;
            uint32_t soff = row * 128 + ((ld_chunk ^ (row & 7)) << 4);
            CP_ASYNC_16(sbase + A_OFF + soff,
                        xa + (size_t)(m0 + row) * KK + k0 + ld_chunk * 8);
        }
        #pragma unroll
        for (int i = 0; i < 4; i++) {
            int row = i * 32 + ld_row;
            uint32_t soff = row * 128 + ((ld_chunk ^ (row & 7)) << 4);
            CP_ASYNC_16(sbase + B_OFF + soff,
                        wb + (size_t)(n0 + row) * KK + k0 + ld_chunk * 8);
        }
    };

    // prologue: 2 stages in flight
    load_stage(0, 0); CP_ASYNC_COMMIT();
    load_stage(1, 1); CP_ASYNC_COMMIT();

    // --- ldmatrix per-thread address components ---
    const int mt = lane >> 3;            // matrix index 0..3
    const int lrow = lane & 7;
    // A mats: (m+0,kc0) (m+8,kc0) (m+0,kc1) (m+8,kc1)
    const int a_row = warp_m * 64 + lrow + ((mt & 1) << 3);   // + mi*16
    const int a_koff = mt >> 1;
    // B mats: (n+0,kc0) (n+0,kc1) (n+8,kc0) (n+8,kc1)
    const int b_row = warp_n * 32 + lrow + ((mt >> 1) << 3);  // + nj2*16
    const int b_koff = mt & 1;

    float acc[4][4][4];                  // mi, nj(4 x n8), quad
    #pragma unroll
    for (int mi = 0; mi < 4; mi++)
        #pragma unroll
        for (int nj = 0; nj < 4; nj++)
            #pragma unroll
            for (int q = 0; q < 4; q++) acc[mi][nj][q] = 0.f;

    for (int c = 0; c < CHUNKS; c++) {
        CP_ASYNC_WAIT_1();
        __syncthreads();
        if (c + 2 < CHUNKS) load_stage((c + 2) % STAGES, c + 2);
        CP_ASYNC_COMMIT();

        const uint32_t sbase = sb + (c % STAGES) * STAGE_BYTES;

        #pragma unroll
        for (int ks = 0; ks < 4; ks++) {
            // B fragments: 2 x ldmatrix.x4 -> 4 n8 slices
            uint32_t b[2][4];
            #pragma unroll
            for (int nj2 = 0; nj2 < 2; nj2++) {
                int row = b_row + nj2 * 16;
                int kch = ks * 2 + b_koff;
                uint32_t off = row * 128 + ((kch ^ (row & 7)) << 4);
                ldmatrix_x4(b[nj2][0], b[nj2][1], b[nj2][2], b[nj2][3],
                            sbase + B_OFF + off);
            }
            #pragma unroll
            for (int mi = 0; mi < 4; mi++) {
                int row = a_row + mi * 16;
                int kch = ks * 2 + a_koff;
                uint32_t off = row * 128 + ((kch ^ (row & 7)) << 4);
                uint32_t a[4];
                ldmatrix_x4(a[0], a[1], a[2], a[3], sbase + A_OFF + off);
                #pragma unroll
                for (int nj2 = 0; nj2 < 2; nj2++) {
                    mma_f16(acc[mi][nj2 * 2 + 0], a, b[nj2][0], b[nj2][1]);
                    mma_f16(acc[mi][nj2 * 2 + 1], a, b[nj2][2], b[nj2][3]);
                }
            }
        }
        __syncthreads();
    }

    // --- epilogue: += bias, write fp32 ---
    const int qcol = (lane & 3) * 2;
    float2 bv[4];
    #pragma unroll
    for (int nj = 0; nj < 4; nj++)
        bv[nj] = *reinterpret_cast<const float2*>(
            bias + n0 + warp_n * 32 + nj * 8 + qcol);

    #pragma unroll
    for (int mi = 0; mi < 4; mi++) {
        int r0 = m0 + warp_m * 64 + mi * 16 + (lane >> 2);
        float* p0 = out + (size_t)r0 * NN + n0 + warp_n * 32 + qcol;
        float* p1 = p0 + 8 * NN;
        #pragma unroll
        for (int nj = 0; nj < 4; nj++) {
            float2 v0, v1;
            v0.x = acc[mi][nj][0] + bv[nj].x;
            v0.y = acc[mi][nj][1] + bv[nj].y;
            v1.x = acc[mi][nj][2] + bv[nj].x;
            v1.y = acc[mi][nj][3] + bv[nj].y;
            *reinterpret_cast<float2*>(p0 + nj * 8) = v0;
            *reinterpret_cast<float2*>(p1 + nj * 8) = v1;
        }
    }
}

// ---------------------------------------------------------------------------
// Host launch
// ---------------------------------------------------------------------------
extern "C" void kernel_launch(void* const* d_in, const int* in_sizes, int n_in,
                              void* d_out, int out_size) {
    const float* x    = (const float*)d_in[0];
    const float* w    = (const float*)d_in[1];
    const float* bias = (const float*)d_in[2];
    float* out = (float*)d_out;

    void *p_xa = nullptr, *p_wb = nullptr;
    cudaGetSymbolAddress(&p_xa, g_xa);
    cudaGetSymbolAddress(&p_wb, g_wb);

    const int n4 = MM * KK / 4;
    convert_x_kernel<<<n4 / 256, 256>>>((const float4*)x, (uint2*)p_xa);
    convert_w_kernel<<<n4 / 256, 256>>>((const float4*)w, (uint2*)p_wb);

    static bool attr_set = false;
    if (!attr_set) {
        cudaFuncSetAttribute(bingemm_kernel,
                             cudaFuncAttributeMaxDynamicSharedMemorySize, SMEM_TOTAL);
        attr_set = true;
    }

    dim3 grid(NN / BN, MM / BM);  // (32, 32) = 1024 CTAs
    bingemm_kernel<<<grid, THREADS, SMEM_TOTAL>>>(
        (const __half*)p_xa, (const __half*)p_wb, bias, out);
}

// round 8
// speedup vs baseline: 6.4721x; 1.0481x over previous
#include <cuda_runtime.h>
#include <cuda_fp16.h>
#include <cstdint>

// ============================================================================
// out[M,N] = X[M,K] @ sign(W)[N,K]^T + bias[N],  M=N=K=4096, fp32.
// sm_103 plain PTX target => legacy mma.sync fp16 path.
// History: dual bf16 711us (R3); s8 IMMA 3x slower - banned (R4);
// single fp16 412us (R6); BN=128 + 2 CTA/SM 356us (R7).
// R8: 4 warps x (64x64) warp tile => A-fragment duplication 4x->2x,
// ldmatrix traffic 96->64KB/chunk; L1 port (was exactly co-saturated with
// tensor pipe) now 25% under the HMMA floor.
// ============================================================================

static constexpr int MM = 4096;
static constexpr int NN = 4096;
static constexpr int KK = 4096;

static constexpr int BM = 128;
static constexpr int BN = 128;
static constexpr int BK = 64;            // 64 fp16 = 128B row
static constexpr int STAGES = 3;
static constexpr int CHUNKS = KK / BK;   // 64
static constexpr int THREADS = 128;      // 4 warps: 2 (M) x 2 (N), warp 64x64

// SMEM stage layout (bytes)
static constexpr int A_BYTES = BM * 128;           // 16384
static constexpr int B_BYTES = BN * 128;           // 16384
static constexpr int A_OFF = 0;
static constexpr int B_OFF = A_BYTES;
static constexpr int STAGE_BYTES = A_BYTES + B_BYTES;   // 32768
static constexpr int SMEM_TOTAL = STAGES * STAGE_BYTES; // 98304

// ---------------------------------------------------------------------------
// Scratch (allocation-free)
// ---------------------------------------------------------------------------
__device__ __align__(1024) __half g_xa[(size_t)MM * KK];
__device__ __align__(1024) __half g_wb[(size_t)NN * KK];

// ---------------------------------------------------------------------------
// helpers
// ---------------------------------------------------------------------------
__device__ __forceinline__ uint32_t smem_u32(const void* p) {
    uint32_t a;
    asm("{ .reg .u64 t; cvta.to.shared.u64 t, %1; cvt.u32.u64 %0, t; }"
        : "=r"(a) : "l"(p));
    return a;
}

#define CP_ASYNC_16(dst, src) \
    asm volatile("cp.async.cg.shared.global [%0], [%1], 16;" \
        :: "r"(dst), "l"(src) : "memory")
#define CP_ASYNC_COMMIT() asm volatile("cp.async.commit_group;" ::: "memory")
#define CP_ASYNC_WAIT_1() asm volatile("cp.async.wait_group 1;" ::: "memory")

__device__ __forceinline__ void ldmatrix_x4(uint32_t& r0, uint32_t& r1,
                                            uint32_t& r2, uint32_t& r3,
                                            uint32_t addr) {
    asm volatile("ldmatrix.sync.aligned.m8n8.x4.shared.b16 {%0,%1,%2,%3}, [%4];"
                 : "=r"(r0), "=r"(r1), "=r"(r2), "=r"(r3) : "r"(addr));
}

__device__ __forceinline__ void mma_f16(float* d, const uint32_t* a,
                                        uint32_t b0, uint32_t b1) {
    asm volatile(
        "mma.sync.aligned.m16n8k16.row.col.f32.f16.f16.f32 "
        "{%0,%1,%2,%3}, {%4,%5,%6,%7}, {%8,%9}, {%0,%1,%2,%3};"
        : "+f"(d[0]), "+f"(d[1]), "+f"(d[2]), "+f"(d[3])
        : "r"(a[0]), "r"(a[1]), "r"(a[2]), "r"(a[3]), "r"(b0), "r"(b1));
}

// ---------------------------------------------------------------------------
// Conversion kernels
// ---------------------------------------------------------------------------
__global__ void __launch_bounds__(256) convert_x_kernel(
    const float4* __restrict__ x, uint2* __restrict__ xa) {
    int i = blockIdx.x * 256 + threadIdx.x;
    float4 v = x[i];
    __half2 p01 = __floats2half2_rn(v.x, v.y);
    __half2 p23 = __floats2half2_rn(v.z, v.w);
    uint2 p;
    p.x = *reinterpret_cast<uint32_t*>(&p01);
    p.y = *reinterpret_cast<uint32_t*>(&p23);
    xa[i] = p;
}

__global__ void __launch_bounds__(256) convert_w_kernel(
    const float4* __restrict__ w, uint2* __restrict__ wb) {
    int i = blockIdx.x * 256 + threadIdx.x;
    float4 v = w[i];
    float s0 = (v.x > 0.f) ? 1.f : ((v.x < 0.f) ? -1.f : 0.f);
    float s1 = (v.y > 0.f) ? 1.f : ((v.y < 0.f) ? -1.f : 0.f);
    float s2 = (v.z > 0.f) ? 1.f : ((v.z < 0.f) ? -1.f : 0.f);
    float s3 = (v.w > 0.f) ? 1.f : ((v.w < 0.f) ? -1.f : 0.f);
    __half2 p01 = __floats2half2_rn(s0, s1);
    __half2 p23 = __floats2half2_rn(s2, s3);
    uint2 p;
    p.x = *reinterpret_cast<uint32_t*>(&p01);
    p.y = *reinterpret_cast<uint32_t*>(&p23);
    wb[i] = p;
}

// ---------------------------------------------------------------------------
// GEMM kernel (single fp16 pass, 4 warps, 2 CTAs/SM)
// ---------------------------------------------------------------------------
__global__ void __launch_bounds__(THREADS, 2)
bingemm_kernel(const __half* __restrict__ xa,
               const __half* __restrict__ wb,
               const float* __restrict__ bias,
               float* __restrict__ out) {
    extern __shared__ __align__(1024) char smem[];
    const uint32_t sb = smem_u32(smem);

    const int tid = threadIdx.x;
    const int wid = tid >> 5;
    const int lane = tid & 31;
    const int warp_m = wid & 1;    // 0..1 -> 64 rows
    const int warp_n = wid >> 1;   // 0..1 -> 64 cols
    const int m0 = blockIdx.y * BM;
    const int n0 = blockIdx.x * BN;

    // --- cp.async tile loader (row = 128B = 8 x 16B chunks, xor swizzle) ---
    const int ld_row = tid >> 3;   // 0..15
    const int ld_chunk = tid & 7;  // 0..7

    auto load_stage = [&](int stage, int c) {
        const uint32_t sbase = sb + stage * STAGE_BYTES;
        const int k0 = c * BK;
        #pragma unroll
        for (int i = 0; i < 8; i++) {
            int row = i * 16 + ld_row;
            uint32_t soff = row * 128 + ((ld_chunk ^ (row & 7)) << 4);
            CP_ASYNC_16(sbase + A_OFF + soff,
                        xa + (size_t)(m0 + row) * KK + k0 + ld_chunk * 8);
        }
        #pragma unroll
        for (int i = 0; i < 8; i++) {
            int row = i * 16 + ld_row;
            uint32_t soff = row * 128 + ((ld_chunk ^ (row & 7)) << 4);
            CP_ASYNC_16(sbase + B_OFF + soff,
                        wb + (size_t)(n0 + row) * KK + k0 + ld_chunk * 8);
        }
    };

    // prologue: 2 stages in flight
    load_stage(0, 0); CP_ASYNC_COMMIT();
    load_stage(1, 1); CP_ASYNC_COMMIT();

    // --- ldmatrix per-thread address components ---
    const int mt = lane >> 3;            // matrix index 0..3
    const int lrow = lane & 7;
    // A mats: (m+0,kc0) (m+8,kc0) (m+0,kc1) (m+8,kc1)
    const int a_row = warp_m * 64 + lrow + ((mt & 1) << 3);   // + mi*16
    const int a_koff = mt >> 1;
    // B mats: (n+0,kc0) (n+0,kc1) (n+8,kc0) (n+8,kc1)
    const int b_row = warp_n * 64 + lrow + ((mt >> 1) << 3);  // + nj2*16
    const int b_koff = mt & 1;

    float acc[4][8][4];                  // mi, nj (8 x n8), quad
    #pragma unroll
    for (int mi = 0; mi < 4; mi++)
        #pragma unroll
        for (int nj = 0; nj < 8; nj++)
            #pragma unroll
            for (int q = 0; q < 4; q++) acc[mi][nj][q] = 0.f;

    for (int c = 0; c < CHUNKS; c++) {
        CP_ASYNC_WAIT_1();
        __syncthreads();
        if (c + 2 < CHUNKS) load_stage((c + 2) % STAGES, c + 2);
        CP_ASYNC_COMMIT();

        const uint32_t sbase = sb + (c % STAGES) * STAGE_BYTES;

        #pragma unroll
        for (int ks = 0; ks < 4; ks++) {
            // B fragments: 4 x ldmatrix.x4 -> 8 n8 slices
            uint32_t b[4][4];
            #pragma unroll
            for (int nj2 = 0; nj2 < 4; nj2++) {
                int row = b_row + nj2 * 16;
                int kch = ks * 2 + b_koff;
                uint32_t off = row * 128 + ((kch ^ (row & 7)) << 4);
                ldmatrix_x4(b[nj2][0], b[nj2][1], b[nj2][2], b[nj2][3],
                            sbase + B_OFF + off);
            }
            // A fragments just-in-time per 16-row slice
            #pragma unroll
            for (int mi = 0; mi < 4; mi++) {
                int row = a_row + mi * 16;
                int kch = ks * 2 + a_koff;
                uint32_t off = row * 128 + ((kch ^ (row & 7)) << 4);
                uint32_t a[4];
                ldmatrix_x4(a[0], a[1], a[2], a[3], sbase + A_OFF + off);
                #pragma unroll
                for (int nj2 = 0; nj2 < 4; nj2++) {
                    mma_f16(acc[mi][nj2 * 2 + 0], a, b[nj2][0], b[nj2][1]);
                    mma_f16(acc[mi][nj2 * 2 + 1], a, b[nj2][2], b[nj2][3]);
                }
            }
        }
        __syncthreads();
    }

    // --- epilogue: += bias, write fp32 ---
    const int qcol = (lane & 3) * 2;
    float2 bv[8];
    #pragma unroll
    for (int nj = 0; nj < 8; nj++)
        bv[nj] = *reinterpret_cast<const float2*>(
            bias + n0 + warp_n * 64 + nj * 8 + qcol);

    #pragma unroll
    for (int mi = 0; mi < 4; mi++) {
        int r0 = m0 + warp_m * 64 + mi * 16 + (lane >> 2);
        float* p0 = out + (size_t)r0 * NN + n0 + warp_n * 64 + qcol;
        float* p1 = p0 + 8 * NN;
        #pragma unroll
        for (int nj = 0; nj < 8; nj++) {
            float2 v0, v1;
            v0.x = acc[mi][nj][0] + bv[nj].x;
            v0.y = acc[mi][nj][1] + bv[nj].y;
            v1.x = acc[mi][nj][2] + bv[nj].x;
            v1.y = acc[mi][nj][3] + bv[nj].y;
            *reinterpret_cast<float2*>(p0 + nj * 8) = v0;
            *reinterpret_cast<float2*>(p1 + nj * 8) = v1;
        }
    }
}

// ---------------------------------------------------------------------------
// Host launch
// ---------------------------------------------------------------------------
extern "C" void kernel_launch(void* const* d_in, const int* in_sizes, int n_in,
                              void* d_out, int out_size) {
    const float* x    = (const float*)d_in[0];
    const float* w    = (const float*)d_in[1];
    const float* bias = (const float*)d_in[2];
    float* out = (float*)d_out;

    void *p_xa = nullptr, *p_wb = nullptr;
    cudaGetSymbolAddress(&p_xa, g_xa);
    cudaGetSymbolAddress(&p_wb, g_wb);

    const int n4 = MM * KK / 4;
    convert_x_kernel<<<n4 / 256, 256>>>((const float4*)x, (uint2*)p_xa);
    convert_w_kernel<<<n4 / 256, 256>>>((const float4*)w, (uint2*)p_wb);

    static bool attr_set = false;
    if (!attr_set) {
        cudaFuncSetAttribute(bingemm_kernel,
                             cudaFuncAttributeMaxDynamicSharedMemorySize, SMEM_TOTAL);
        attr_set = true;
    }

    dim3 grid(NN / BN, MM / BM);  // (32, 32) = 1024 CTAs
    bingemm_kernel<<<grid, THREADS, SMEM_TOTAL>>>(
        (const __half*)p_xa, (const __half*)p_wb, bias, out);
}